// round 2
// baseline (speedup 1.0000x reference)
#include <cuda_runtime.h>
#include <math.h>

#define B 8
#define C 48
#define HH 256
#define WW 256
#define NPIX (HH*WW)
#define HEADS 8
#define DH 6
#define SCALE 0.40824829046386296f  /* 6^-0.5 */
#define EPSN 1e-12f

#define TX 32
#define TY 16
#define TPX (TX*TY)      /* 512 */
#define HX (TX+2)        /* 34 */
#define HY (TY+2)        /* 18 */
#define HALO (HX*HY)     /* 612 */
#define NT 512
#define TILES_X (WW/TX)  /* 8 */
#define TILES_Y (HH/TY)  /* 16 */
#define NTILES (TILES_X*TILES_Y) /* 128 */

/* scratch (no allocations allowed -> device globals) */
__device__ float g_v[B*C*NPIX];                 /* ~96 MB */
__device__ float g_part[B*NTILES*HEADS*48];     /* per-tile gram partials (deterministic reduce) */
__device__ float g_gram[B*HEADS*48];
__device__ float g_M[B*C*C];

/* dynamic smem layout (float offsets) */
#define OFF_XS 0
#define SZ_XS (C*HALO)             /* 29376 */
#define OFF_WPW (OFF_XS+SZ_XS)     /* 29376 */
#define SZ_WPW (144*48)            /* 6912 */
#define OFF_WD (OFF_WPW+SZ_WPW)    /* 36288 */
#define SZ_WD (144*9)              /* 1296 */
#define OFF_PWS (OFF_WD+SZ_WD)     /* 37584 */
#define SZ_PWS HALO                /* 612 */
#define OFF_DWS (OFF_PWS+SZ_PWS)   /* 38196 */
#define SZ_DWS (12*TPX)            /* 6144 */
#define SMEM_FLOATS (OFF_DWS+SZ_DWS) /* 44340 -> 177360 B */

__global__ __launch_bounds__(NT, 1)
void k_fused(const float* __restrict__ x, const float* __restrict__ wqkv,
             const float* __restrict__ wdw)
{
    extern __shared__ float sm[];
    float* xs  = sm + OFF_XS;
    float* wpw = sm + OFF_WPW;
    float* wd  = sm + OFF_WD;
    float* pws = sm + OFF_PWS;
    float* dws = sm + OFF_DWS;

    const int tid = threadIdx.x;
    const int b = blockIdx.z;
    const int ox0 = blockIdx.x * TX, oy0 = blockIdx.y * TY;

    /* stage weights */
    for (int i = tid; i < 144*48; i += NT) wpw[i] = wqkv[i];
    for (int i = tid; i < 144*9;  i += NT) wd[i]  = wdw[i];

    /* stage x halo tile (zero-padded SAME) */
    const float* xb = x + (size_t)b * C * NPIX;
    for (int i = tid; i < C*HALO; i += NT) {
        int c = i / HALO, p = i % HALO;
        int hy = p / HX, hx = p % HX;
        int gy = oy0 - 1 + hy, gx = ox0 - 1 + hx;
        float v = 0.f;
        if ((unsigned)gy < (unsigned)HH && (unsigned)gx < (unsigned)WW)
            v = xb[c*NPIX + gy*WW + gx];
        xs[i] = v;
    }
    __syncthreads();

    const int oy = tid / TX, ox = tid % TX;
    const int p0 = tid;
    const bool has1 = (tid < HALO - NT);     /* tid < 100 */
    const int p1 = has1 ? tid + NT : tid;
    const int warp = tid >> 5, lane = tid & 31;
    const int tileLin = blockIdx.y * TILES_X + blockIdx.x;

    for (int h = 0; h < HEADS; ++h) {
        /* 6 q-channels then 6 k-channels of head h */
        for (int j = 0; j < 12; ++j) {
            const int c = (j < 6) ? (h*DH + j) : (C + h*DH + (j - 6));
            /* pointwise conv at this thread's 1-2 halo pixels */
            const float4* w4 = reinterpret_cast<const float4*>(wpw + c*48);
            float a0 = 0.f, a1 = 0.f;
            #pragma unroll
            for (int i = 0; i < 12; ++i) {
                float4 w = w4[i];
                const float* xp = xs + (4*i)*HALO;
                a0 += w.x * xp[p0];          a1 += w.x * xp[p1];
                a0 += w.y * xp[HALO + p0];   a1 += w.y * xp[HALO + p1];
                a0 += w.z * xp[2*HALO + p0]; a1 += w.z * xp[2*HALO + p1];
                a0 += w.w * xp[3*HALO + p0]; a1 += w.w * xp[3*HALO + p1];
            }
            __syncthreads();                 /* prior pws readers done */
            pws[p0] = a0;
            if (has1) pws[p1] = a1;
            __syncthreads();
            /* 3x3 depthwise at this thread's output pixel */
            const float* wr = wd + c*9;
            const float* pp = pws + oy*HX + ox;
            float dv = wr[0]*pp[0]      + wr[1]*pp[1]        + wr[2]*pp[2]
                     + wr[3]*pp[HX]     + wr[4]*pp[HX+1]     + wr[5]*pp[HX+2]
                     + wr[6]*pp[2*HX]   + wr[7]*pp[2*HX+1]   + wr[8]*pp[2*HX+2];
            dws[j*TPX + tid] = dv;
        }
        __syncthreads();
        /* gram + norms: 48 combos over 16 warps x 3 */
        #pragma unroll
        for (int i = 0; i < 3; ++i) {
            int combo = warp*3 + i;
            const float *pa, *pb;
            if (combo < 36)      { pa = dws + (combo/6)*TPX;      pb = dws + (6 + combo%6)*TPX; }
            else if (combo < 42) { pa = dws + (combo-36)*TPX;     pb = pa; }
            else                 { pa = dws + (6 + combo-42)*TPX; pb = pa; }
            float s = 0.f;
            #pragma unroll
            for (int pidx = 0; pidx < TPX/32; ++pidx)
                s += pa[lane + pidx*32] * pb[lane + pidx*32];
            #pragma unroll
            for (int off = 16; off; off >>= 1)
                s += __shfl_down_sync(0xffffffffu, s, off);
            if (lane == 0)
                g_part[((size_t)(b*NTILES + tileLin))*(HEADS*48) + h*48 + combo] = s;
        }
        /* next j-loop has 2 barriers before touching dws -> gram reads protected */
    }

    /* v channels: pw+dw, store to scratch */
    float* vb = g_v + (size_t)b * C * NPIX + (oy0+oy)*WW + (ox0+ox);
    for (int cv = 0; cv < C; ++cv) {
        const int c = 2*C + cv;   /* 96..143 */
        const float4* w4 = reinterpret_cast<const float4*>(wpw + c*48);
        float a0 = 0.f, a1 = 0.f;
        #pragma unroll
        for (int i = 0; i < 12; ++i) {
            float4 w = w4[i];
            const float* xp = xs + (4*i)*HALO;
            a0 += w.x * xp[p0];          a1 += w.x * xp[p1];
            a0 += w.y * xp[HALO + p0];   a1 += w.y * xp[HALO + p1];
            a0 += w.z * xp[2*HALO + p0]; a1 += w.z * xp[2*HALO + p1];
            a0 += w.w * xp[3*HALO + p0]; a1 += w.w * xp[3*HALO + p1];
        }
        __syncthreads();
        pws[p0] = a0;
        if (has1) pws[p1] = a1;
        __syncthreads();
        const float* wr = wd + c*9;
        const float* pp = pws + oy*HX + ox;
        float dv = wr[0]*pp[0]      + wr[1]*pp[1]        + wr[2]*pp[2]
                 + wr[3]*pp[HX]     + wr[4]*pp[HX+1]     + wr[5]*pp[HX+2]
                 + wr[6]*pp[2*HX]   + wr[7]*pp[2*HX+1]   + wr[8]*pp[2*HX+2];
        vb[cv*NPIX] = dv;
    }
}

/* deterministic reduction of per-tile partials */
__global__ void k_reduce()
{
    int idx = blockIdx.x * blockDim.x + threadIdx.x;
    if (idx >= B*HEADS*48) return;
    int b = idx / (HEADS*48);
    int rem = idx % (HEADS*48);
    const float* p = g_part + (size_t)b*NTILES*(HEADS*48) + rem;
    float s = 0.f;
    for (int t = 0; t < NTILES; ++t) s += p[t*(HEADS*48)];
    g_gram[idx] = s;
}

/* per-batch: normalize, softmax, fold attn into M = Wproj * blockdiag(attn) */
__global__ void k_attn(const float* __restrict__ wproj)
{
    int b = blockIdx.x, tid = threadIdx.x;
    __shared__ float attn_s[HEADS][36];
    if (tid < HEADS*DH) {
        int h = tid / DH, d = tid % DH;
        const float* g = g_gram + (b*HEADS + h)*48;
        float qn = fmaxf(sqrtf(g[36 + d]), EPSN);
        float a[6]; float m = -1e30f;
        #pragma unroll
        for (int e = 0; e < 6; ++e) {
            float kn = fmaxf(sqrtf(g[42 + e]), EPSN);
            a[e] = g[d*6+e] * SCALE / (qn * kn);
            m = fmaxf(m, a[e]);
        }
        float s = 0.f;
        #pragma unroll
        for (int e = 0; e < 6; ++e) { a[e] = expf(a[e]-m); s += a[e]; }
        float inv = 1.f / s;
        #pragma unroll
        for (int e = 0; e < 6; ++e) attn_s[h][d*6+e] = a[e]*inv;
    }
    __syncthreads();
    for (int idx = tid; idx < C*C; idx += blockDim.x) {
        int c = idx / C, c2 = idx % C;
        int h2 = c2 / DH, e = c2 % DH;
        float s = 0.f;
        #pragma unroll
        for (int d = 0; d < 6; ++d)
            s += wproj[c*C + h2*DH + d] * attn_s[h2][d*6+e];
        g_M[b*C*C + idx] = s;
    }
}

/* out = M[b] @ v  (per pixel 48x48 matvec) */
__global__ __launch_bounds__(256)
void k_proj(float* __restrict__ out)
{
    int b = blockIdx.y;
    int n = blockIdx.x * 256 + threadIdx.x;
    __shared__ float Ms[C*C];
    for (int i = threadIdx.x; i < C*C; i += 256) Ms[i] = g_M[b*C*C + i];
    __syncthreads();
    float vv[C];
    const float* vp = g_v + (size_t)b*C*NPIX + n;
    #pragma unroll
    for (int c2 = 0; c2 < C; ++c2) vv[c2] = vp[c2*NPIX];
    float* op = out + (size_t)b*C*NPIX + n;
    #pragma unroll 4
    for (int c = 0; c < C; ++c) {
        const float4* mr = reinterpret_cast<const float4*>(Ms + c*C);
        float s = 0.f;
        #pragma unroll
        for (int i = 0; i < 12; ++i) {
            float4 w = mr[i];
            s += w.x*vv[4*i] + w.y*vv[4*i+1] + w.z*vv[4*i+2] + w.w*vv[4*i+3];
        }
        op[c*NPIX] = s;
    }
}

extern "C" void kernel_launch(void* const* d_in, const int* in_sizes, int n_in,
                              void* d_out, int out_size)
{
    const float* x     = (const float*)d_in[0];
    const float* wqkv  = (const float*)d_in[1];
    const float* wdw   = (const float*)d_in[2];
    const float* wproj = (const float*)d_in[3];
    float* out = (float*)d_out;

    cudaFuncSetAttribute(k_fused, cudaFuncAttributeMaxDynamicSharedMemorySize,
                         SMEM_FLOATS * (int)sizeof(float));

    dim3 g1(TILES_X, TILES_Y, B);
    k_fused<<<g1, NT, SMEM_FLOATS * sizeof(float)>>>(x, wqkv, wdw);
    k_reduce<<<(B*HEADS*48 + 255)/256, 256>>>();
    k_attn<<<B, 256>>>(wproj);
    dim3 g3(NPIX/256, B);
    k_proj<<<g3, 256>>>(out);
}

// round 3
// speedup vs baseline: 1.8523x; 1.8523x over previous
#include <cuda_runtime.h>
#include <math.h>

#define B 8
#define C 48
#define C3 144
#define HH 256
#define WW 256
#define NPIX (HH*WW)
#define HEADS 8
#define DH 6
#define SCALE 0.40824829046386296f  /* 6^-0.5 */
#define EPSN 1e-12f

/* ---- scratch (device globals; no allocations allowed) ---- */
__device__ float g_qkv[(size_t)B*C3*NPIX];   /* ~301 MB pw output */
__device__ float g_v[(size_t)B*C*NPIX];      /* ~96 MB dw(v) */
#define NTIL 256                              /* 16x16 tiles of 16x16 */
__device__ float g_part[B*NTIL*HEADS*48];
__device__ float g_gram[B*HEADS*48];
__device__ float g_M[B*C*C];

/* ================= k_pw: qkv[144][n] = W[144][48] @ x[48][n] ============ */
#define PWN 128                /* pixel tile */
#define PW_TX 32
#define PW_TY 12
#define PW_NT (PW_TX*PW_TY)    /* 384 */
/* dyn smem: xs[48][128] + wT[48][144] */
#define PW_XS 0
#define PW_WT (48*PWN)
#define PW_SMF (48*PWN + 48*C3)   /* 13056 floats = 52224 B */

__global__ __launch_bounds__(PW_NT, 2)
void k_pw(const float* __restrict__ x, const float* __restrict__ wqkv)
{
    extern __shared__ float sm[];
    float* xs = sm + PW_XS;
    float* wT = sm + PW_WT;

    const int tid = threadIdx.x;
    const int tx = tid & 31, ty = tid >> 5;        /* warp == ty */
    const int b = blockIdx.y;
    const int n0 = blockIdx.x * PWN;

    /* stage x tile [48][128] (coalesced rows) */
    const float* xb = x + (size_t)b*C*NPIX + n0;
    for (int i = tid; i < C*PWN; i += PW_NT)
        xs[i] = xb[(size_t)(i >> 7)*NPIX + (i & 127)];
    /* stage transposed weights wT[cin][cout] */
    for (int i = tid; i < C3*C; i += PW_NT)
        wT[(i % C)*C3 + (i / C)] = wqkv[i];
    __syncthreads();

    float4 acc[12];
    #pragma unroll
    for (int j = 0; j < 12; ++j) acc[j] = make_float4(0.f,0.f,0.f,0.f);

    const float4* xcol = reinterpret_cast<const float4*>(xs) + tx;   /* stride 32 float4 per row */
    const float*  wrow = wT + ty*12;

    #pragma unroll 4
    for (int cin = 0; cin < C; ++cin) {
        float4 xv = xcol[cin*(PWN/4)];
        const float4* w4 = reinterpret_cast<const float4*>(wrow + cin*C3);
        float4 w0 = w4[0], w1 = w4[1], w2 = w4[2];
        acc[0].x += w0.x*xv.x; acc[0].y += w0.x*xv.y; acc[0].z += w0.x*xv.z; acc[0].w += w0.x*xv.w;
        acc[1].x += w0.y*xv.x; acc[1].y += w0.y*xv.y; acc[1].z += w0.y*xv.z; acc[1].w += w0.y*xv.w;
        acc[2].x += w0.z*xv.x; acc[2].y += w0.z*xv.y; acc[2].z += w0.z*xv.z; acc[2].w += w0.z*xv.w;
        acc[3].x += w0.w*xv.x; acc[3].y += w0.w*xv.y; acc[3].z += w0.w*xv.z; acc[3].w += w0.w*xv.w;
        acc[4].x += w1.x*xv.x; acc[4].y += w1.x*xv.y; acc[4].z += w1.x*xv.z; acc[4].w += w1.x*xv.w;
        acc[5].x += w1.y*xv.x; acc[5].y += w1.y*xv.y; acc[5].z += w1.y*xv.z; acc[5].w += w1.y*xv.w;
        acc[6].x += w1.z*xv.x; acc[6].y += w1.z*xv.y; acc[6].z += w1.z*xv.z; acc[6].w += w1.z*xv.w;
        acc[7].x += w1.w*xv.x; acc[7].y += w1.w*xv.y; acc[7].z += w1.w*xv.z; acc[7].w += w1.w*xv.w;
        acc[8].x += w2.x*xv.x; acc[8].y += w2.x*xv.y; acc[8].z += w2.x*xv.z; acc[8].w += w2.x*xv.w;
        acc[9].x += w2.y*xv.x; acc[9].y += w2.y*xv.y; acc[9].z += w2.y*xv.z; acc[9].w += w2.y*xv.w;
        acc[10].x += w2.z*xv.x; acc[10].y += w2.z*xv.y; acc[10].z += w2.z*xv.z; acc[10].w += w2.z*xv.w;
        acc[11].x += w2.w*xv.x; acc[11].y += w2.w*xv.y; acc[11].z += w2.w*xv.z; acc[11].w += w2.w*xv.w;
    }

    float* ob = g_qkv + (size_t)b*C3*NPIX + n0 + tx*4;
    #pragma unroll
    for (int j = 0; j < 12; ++j) {
        int cout = ty*12 + j;
        *reinterpret_cast<float4*>(ob + (size_t)cout*NPIX) = acc[j];
    }
}

/* ========== k_dw: depthwise 3x3 + gram partials (q,k) / v store ========== */
#define TIL 16
#define HLO 18
#define HLOSZ (HLO*HLO)   /* 324 */
#define DW_NT 256

__global__ __launch_bounds__(DW_NT)
void k_dw(const float* __restrict__ wdw)
{
    __shared__ float halo[12][HLOSZ];
    __shared__ float dws[12][DW_NT];
    __shared__ float wds[12*9];

    const int tid = threadIdx.x;
    const int z = blockIdx.z;
    const int b = z / 14, g = z % 14;
    const bool isHead = (g < 8);
    const int nch = isHead ? 12 : 8;
    const int oy0 = blockIdx.y * TIL, ox0 = blockIdx.x * TIL;
    const int oy = tid / TIL, ox = tid % TIL;

    /* channel list base */
    int chan[12];
    if (isHead) {
        #pragma unroll
        for (int j = 0; j < 6; ++j) { chan[j] = g*DH + j; chan[6+j] = C + g*DH + j; }
    } else {
        #pragma unroll
        for (int j = 0; j < 8; ++j) chan[j] = 2*C + (g-8)*8 + j;
    }

    /* stage dw weights */
    if (tid < nch*9) wds[tid] = wdw[chan[tid/9]*9 + tid%9];

    /* stage halos */
    const float* qb = g_qkv + (size_t)b*C3*NPIX;
    for (int i = tid; i < nch*HLOSZ; i += DW_NT) {
        int ch = i / HLOSZ, p = i % HLOSZ;
        int hy = p / HLO, hx = p % HLO;
        int gy = oy0 - 1 + hy, gx = ox0 - 1 + hx;
        float v = 0.f;
        if ((unsigned)gy < (unsigned)HH && (unsigned)gx < (unsigned)WW)
            v = qb[(size_t)chan[ch]*NPIX + gy*WW + gx];
        halo[ch][p] = v;
    }
    __syncthreads();

    if (isHead) {
        #pragma unroll
        for (int ch = 0; ch < 12; ++ch) {
            const float* w = wds + ch*9;
            const float* p = &halo[ch][oy*HLO + ox];
            dws[ch][tid] = w[0]*p[0]       + w[1]*p[1]         + w[2]*p[2]
                         + w[3]*p[HLO]     + w[4]*p[HLO+1]     + w[5]*p[HLO+2]
                         + w[6]*p[2*HLO]   + w[7]*p[2*HLO+1]   + w[8]*p[2*HLO+2];
        }
        __syncthreads();
        const int warp = tid >> 5, lane = tid & 31;
        const int tileLin = blockIdx.y * (WW/TIL) + blockIdx.x;
        #pragma unroll
        for (int i = 0; i < 6; ++i) {
            int combo = warp*6 + i;
            const float *pa, *pb;
            if (combo < 36)      { pa = dws[combo/6];      pb = dws[6 + combo%6]; }
            else if (combo < 42) { pa = dws[combo-36];     pb = pa; }
            else                 { pa = dws[6 + combo-42]; pb = pa; }
            float s = 0.f;
            #pragma unroll
            for (int k = 0; k < DW_NT/32; ++k)
                s += pa[lane + k*32] * pb[lane + k*32];
            #pragma unroll
            for (int off = 16; off; off >>= 1)
                s += __shfl_down_sync(0xffffffffu, s, off);
            if (lane == 0)
                g_part[((size_t)(b*NTIL + tileLin)*HEADS + g)*48 + combo] = s;
        }
    } else {
        float* vb = g_v + (size_t)b*C*NPIX + (oy0+oy)*WW + (ox0+ox);
        #pragma unroll
        for (int ch = 0; ch < 8; ++ch) {
            const float* w = wds + ch*9;
            const float* p = &halo[ch][oy*HLO + ox];
            float dv = w[0]*p[0]       + w[1]*p[1]         + w[2]*p[2]
                     + w[3]*p[HLO]     + w[4]*p[HLO+1]     + w[5]*p[HLO+2]
                     + w[6]*p[2*HLO]   + w[7]*p[2*HLO+1]   + w[8]*p[2*HLO+2];
            vb[(size_t)(chan[ch]-2*C)*NPIX] = dv;
        }
    }
}

/* ---------------- deterministic gram reduce -------------------- */
__global__ void k_reduce()
{
    int idx = blockIdx.x * blockDim.x + threadIdx.x;
    if (idx >= B*HEADS*48) return;
    int b = idx / (HEADS*48);
    int rem = idx % (HEADS*48);
    const float* p = g_part + (size_t)b*NTIL*(HEADS*48) + rem;
    float s = 0.f;
    for (int t = 0; t < NTIL; ++t) s += p[(size_t)t*(HEADS*48)];
    g_gram[idx] = s;
}

/* ------- softmax + fold attn into M = Wproj * blockdiag(attn) -------- */
__global__ void k_attn(const float* __restrict__ wproj)
{
    int b = blockIdx.x, tid = threadIdx.x;
    __shared__ float attn_s[HEADS][36];
    if (tid < HEADS*DH) {
        int h = tid / DH, d = tid % DH;
        const float* g = g_gram + (b*HEADS + h)*48;
        float qn = fmaxf(sqrtf(g[36 + d]), EPSN);
        float a[6]; float m = -1e30f;
        #pragma unroll
        for (int e = 0; e < 6; ++e) {
            float kn = fmaxf(sqrtf(g[42 + e]), EPSN);
            a[e] = g[d*6+e] * SCALE / (qn * kn);
            m = fmaxf(m, a[e]);
        }
        float s = 0.f;
        #pragma unroll
        for (int e = 0; e < 6; ++e) { a[e] = expf(a[e]-m); s += a[e]; }
        float inv = 1.f / s;
        #pragma unroll
        for (int e = 0; e < 6; ++e) attn_s[h][d*6+e] = a[e]*inv;
    }
    __syncthreads();
    for (int idx = tid; idx < C*C; idx += blockDim.x) {
        int c = idx / C, c2 = idx % C;
        int h2 = c2 / DH, e = c2 % DH;
        float s = 0.f;
        #pragma unroll
        for (int d = 0; d < 6; ++d)
            s += wproj[c*C + h2*DH + d] * attn_s[h2][d*6+e];
        g_M[b*C*C + idx] = s;
    }
}

/* -------------------- out = M[b] @ v ------------------------- */
__global__ __launch_bounds__(256)
void k_proj(float* __restrict__ out)
{
    int b = blockIdx.y;
    int n = blockIdx.x * 256 + threadIdx.x;
    __shared__ float Ms[C*C];
    for (int i = threadIdx.x; i < C*C; i += 256) Ms[i] = g_M[b*C*C + i];
    __syncthreads();
    float vv[C];
    const float* vp = g_v + (size_t)b*C*NPIX + n;
    #pragma unroll
    for (int c2 = 0; c2 < C; ++c2) vv[c2] = vp[(size_t)c2*NPIX];
    float* op = out + (size_t)b*C*NPIX + n;
    #pragma unroll 4
    for (int c = 0; c < C; ++c) {
        const float4* mr = reinterpret_cast<const float4*>(Ms + c*C);
        float s = 0.f;
        #pragma unroll
        for (int i = 0; i < 12; ++i) {
            float4 w = mr[i];
            s += w.x*vv[4*i] + w.y*vv[4*i+1] + w.z*vv[4*i+2] + w.w*vv[4*i+3];
        }
        op[(size_t)c*NPIX] = s;
    }
}

extern "C" void kernel_launch(void* const* d_in, const int* in_sizes, int n_in,
                              void* d_out, int out_size)
{
    const float* x     = (const float*)d_in[0];
    const float* wqkv  = (const float*)d_in[1];
    const float* wdw   = (const float*)d_in[2];
    const float* wproj = (const float*)d_in[3];
    float* out = (float*)d_out;

    cudaFuncSetAttribute(k_pw, cudaFuncAttributeMaxDynamicSharedMemorySize,
                         PW_SMF * (int)sizeof(float));

    dim3 gpw(NPIX/PWN, B);
    k_pw<<<gpw, PW_NT, PW_SMF * sizeof(float)>>>(x, wqkv);

    dim3 gdw(WW/TIL, HH/TIL, B*14);
    k_dw<<<gdw, DW_NT>>>(wdw);

    k_reduce<<<(B*HEADS*48 + 255)/256, 256>>>();
    k_attn<<<B, 256>>>(wproj);

    dim3 gpr(NPIX/256, B);
    k_proj<<<gpr, 256>>>(out);
}